// round 3
// baseline (speedup 1.0000x reference)
#include <cuda_runtime.h>
#include <cstdint>

#define TT 512
#define BB 256
#define HH 64
#define GG 256     // 4*H
#define RROWS 2    // batch rows per recurrence CTA -> 128 CTAs

// Scratch (device globals; no allocation in kernel_launch)
__device__ float g_gx[(size_t)TT * BB * GG];   // [T][B][4H] permuted col order
__device__ float g_hA[(size_t)TT * BB * HH];   // [T][B][H]
__device__ float g_hB[(size_t)TT * BB * HH];

// ---- packed fp32x2 helpers (Blackwell FFMA2 via PTX) ----------------------
__device__ __forceinline__ unsigned long long ffma2(unsigned long long a,
                                                    unsigned long long b,
                                                    unsigned long long c) {
    unsigned long long d;
    asm("fma.rn.f32x2 %0, %1, %2, %3;" : "=l"(d) : "l"(a), "l"(b), "l"(c));
    return d;
}
__device__ __forceinline__ unsigned long long fadd2(unsigned long long a,
                                                    unsigned long long b) {
    unsigned long long d;
    asm("add.rn.f32x2 %0, %1, %2;" : "=l"(d) : "l"(a), "l"(b));
    return d;
}
__device__ __forceinline__ float2 unpack2(unsigned long long v) {
    float2 r;
    asm("mov.b64 {%0, %1}, %2;" : "=f"(r.x), "=f"(r.y) : "l"(v));
    return r;
}

// gate index permutation: slot q <-> (j = q>>2, g = q&3), torch row = g*64+j
__device__ __forceinline__ int perm_row(int q) { return (q & 3) * 64 + (q >> 2); }

// ---------------------------------------------------------------------------
// Layer 0 input projection (d_in = 2), writes permuted gx layout.
// grid = T, block = 256
// ---------------------------------------------------------------------------
__global__ __launch_bounds__(256) void lstm_gx0_kernel(
    const float* __restrict__ x,      // [B][T][2]
    const float* __restrict__ Wih,    // [256][2]
    const float* __restrict__ bih,
    const float* __restrict__ bhh,
    float* __restrict__ gxout)        // [T][B][256] permuted
{
    __shared__ float xs[2 * BB];
    const int t = blockIdx.x;
    const int tid = threadIdx.x;
    const int wr = perm_row(tid);

    xs[2 * tid]     = x[((size_t)tid * TT + t) * 2 + 0];
    xs[2 * tid + 1] = x[((size_t)tid * TT + t) * 2 + 1];
    const float w0   = Wih[wr * 2];
    const float w1   = Wih[wr * 2 + 1];
    const float bias = bih[wr] + bhh[wr];
    __syncthreads();

    float* op = gxout + (size_t)t * BB * GG + tid;
#pragma unroll 4
    for (int r = 0; r < BB; r++) {
        op[r * GG] = fmaf(xs[2 * r], w0, fmaf(xs[2 * r + 1], w1, bias));
    }
}

// ---------------------------------------------------------------------------
// Layers 1..4 input projection: [T*B,64] x [64,256] + bias, FFMA2 packed.
// Writes permuted gx layout. 8-row accumulation blocks for ILP.
// grid = T*B/64, block = 256.
// ---------------------------------------------------------------------------
__global__ __launch_bounds__(256, 2) void lstm_gx_kernel(
    const float* __restrict__ xseq,   // [T][B][64]
    const float* __restrict__ Wih,    // [256][64]
    const float* __restrict__ bih,
    const float* __restrict__ bhh,
    float* __restrict__ gxout)        // [T][B][256] permuted
{
    __shared__ float4 xs4[64 * 16];   // 64 rows x 64 floats
    const int tid = threadIdx.x;
    const size_t base = (size_t)blockIdx.x * 64;
    const int wr = perm_row(tid);

    const float4* xin = reinterpret_cast<const float4*>(xseq + base * HH);
    for (int i = tid; i < 64 * 16; i += 256) xs4[i] = xin[i];

    // W row as 32 packed f32x2
    unsigned long long w[32];
    {
        const double2* wp = reinterpret_cast<const double2*>(Wih + wr * HH);
#pragma unroll
        for (int i = 0; i < 16; i++) {
            double2 d = wp[i];
            w[2 * i]     = __double_as_longlong(d.x);
            w[2 * i + 1] = __double_as_longlong(d.y);
        }
    }
    const float bias = bih[wr] + bhh[wr];
    __syncthreads();

    const double2* xsd = reinterpret_cast<const double2*>(xs4);
    float* op = gxout + base * GG + tid;
#pragma unroll 1
    for (int r0 = 0; r0 < 64; r0 += 8) {
        unsigned long long acc[8];
#pragma unroll
        for (int r = 0; r < 8; r++) acc[r] = 0ull;
#pragma unroll
        for (int i = 0; i < 16; i++) {
            const unsigned long long wl = w[2 * i], wh = w[2 * i + 1];
#pragma unroll
            for (int r = 0; r < 8; r++) {
                double2 xv = xsd[(r0 + r) * 16 + i];
                acc[r] = ffma2(wl, __double_as_longlong(xv.x), acc[r]);
                acc[r] = ffma2(wh, __double_as_longlong(xv.y), acc[r]);
            }
        }
#pragma unroll
        for (int r = 0; r < 8; r++) {
            float2 s = unpack2(acc[r]);
            op[(r0 + r) * GG] = bias + s.x + s.y;
        }
    }
}

// ---------------------------------------------------------------------------
// Recurrence: 512 threads, thread = (batch row r, hidden j, gate g).
// Each thread does ONE 64-length packed dot per step; quad shuffles gather
// the 4 activated gates; one barrier per step; h double-buffered in smem.
// grid = 128, block = 512.
// ---------------------------------------------------------------------------
__global__ __launch_bounds__(512, 1) void lstm_rec_kernel(
    const float* __restrict__ gx,     // [T][B][256] permuted
    const float* __restrict__ Whh,    // [256][64]
    float* __restrict__ hout)         // [T][B][64]
{
    __shared__ float h_s[2][RROWS * HH];
    const int tid = threadIdx.x;
    const int r = tid >> 8;           // batch row within CTA (0/1)
    const int q = tid & 255;          // gate slot
    const int j = q >> 2, g = q & 3;
    const int row0 = blockIdx.x * RROWS;
    const int wr = g * 64 + j;        // torch gate row

    // W_hh row as 32 packed f32x2
    unsigned long long w[32];
    {
        const double2* wp = reinterpret_cast<const double2*>(Whh + wr * HH);
#pragma unroll
        for (int i = 0; i < 16; i++) {
            double2 d = wp[i];
            w[2 * i]     = __double_as_longlong(d.x);
            w[2 * i + 1] = __double_as_longlong(d.y);
        }
    }

    float c = 0.0f;
    if (tid < RROWS * HH) h_s[0][tid] = 0.0f;
    __syncthreads();

    float gxv = gx[((size_t)0 * BB + row0 + r) * GG + q];

    const float isG = (g == 2) ? 1.0f : 0.0f;   // tanh gate selector
    const float sc  = 1.0f + isG;

    for (int t = 0; t < TT; t++) {
        const int p = t & 1;
        // prefetch next gx (consumed after the barrier)
        float nx = 0.0f;
        if (t + 1 < TT)
            nx = __ldg(&gx[((size_t)(t + 1) * BB + row0 + r) * GG + q]);

        // packed dot: gate = gx + W_row . h(r)
        unsigned long long a = 0ull, b = 0ull;
        const double2* hp = reinterpret_cast<const double2*>(h_s[p] + r * HH);
#pragma unroll
        for (int i = 0; i < 16; i++) {
            double2 hv = hp[i];
            a = ffma2(w[2 * i],     __double_as_longlong(hv.x), a);
            b = ffma2(w[2 * i + 1], __double_as_longlong(hv.y), b);
        }
        float2 s = unpack2(fadd2(a, b));
        const float v = gxv + s.x + s.y;

        // branchless activation: sigmoid for g in {0,1,3}, tanh for g==2
        const float e = __expf(-sc * v);
        const float act = sc / (1.0f + e) - isG;

        // quad gather (gates i,f,g,o live in lanes 0..3 of each quad)
        const unsigned m = 0xffffffffu;
        const float ig = __shfl_sync(m, act, 0, 4);
        const float fg = __shfl_sync(m, act, 1, 4);
        const float Gg = __shfl_sync(m, act, 2, 4);
        const float og = __shfl_sync(m, act, 3, 4);

        c = fmaf(fg, c, ig * Gg);
        const float tc = 2.0f / (1.0f + __expf(-2.0f * c)) - 1.0f;
        const float hv = og * tc;

        if (g == 0) {
            h_s[p ^ 1][r * HH + j] = hv;
            hout[((size_t)t * BB + row0 + r) * HH + j] = hv;
        }
        __syncthreads();   // the ONLY barrier per step
        gxv = nx;
    }
}

// ---------------------------------------------------------------------------
// Final linear head. grid = T, block = 256.
// ---------------------------------------------------------------------------
__global__ __launch_bounds__(256) void lstm_lin_kernel(
    const float* __restrict__ hseq,   // [T][B][64]
    const float* __restrict__ Wl,     // [64]
    const float* __restrict__ bl,     // [1]
    float* __restrict__ out)          // [B][T]
{
    __shared__ float4 wl4[16];
    const int t = blockIdx.x;
    const int b = threadIdx.x;
    if (threadIdx.x < 16)
        wl4[threadIdx.x] = reinterpret_cast<const float4*>(Wl)[threadIdx.x];
    __syncthreads();

    const float4* hp = reinterpret_cast<const float4*>(hseq + ((size_t)t * BB + b) * HH);
    float acc = bl[0];
#pragma unroll
    for (int k4 = 0; k4 < 16; k4++) {
        const float4 h = hp[k4];
        const float4 w = wl4[k4];
        acc = fmaf(h.x, w.x, acc);
        acc = fmaf(h.y, w.y, acc);
        acc = fmaf(h.z, w.z, acc);
        acc = fmaf(h.w, w.w, acc);
    }
    out[(size_t)b * TT + t] = acc;
}

// ---------------------------------------------------------------------------
extern "C" void kernel_launch(void* const* d_in, const int* in_sizes, int n_in,
                              void* d_out, int out_size)
{
    (void)in_sizes; (void)n_in; (void)out_size;

    const float* x = (const float*)d_in[0];
    const float* Wih[5]; const float* Whh[5]; const float* bih[5]; const float* bhh[5];
    for (int l = 0; l < 5; l++) {
        Wih[l] = (const float*)d_in[1 + 4 * l];
        Whh[l] = (const float*)d_in[2 + 4 * l];
        bih[l] = (const float*)d_in[3 + 4 * l];
        bhh[l] = (const float*)d_in[4 + 4 * l];
    }
    const float* Wl = (const float*)d_in[21];
    const float* bl = (const float*)d_in[22];
    float* out = (float*)d_out;

    float *gx, *hA, *hB;
    cudaGetSymbolAddress((void**)&gx, g_gx);
    cudaGetSymbolAddress((void**)&hA, g_hA);
    cudaGetSymbolAddress((void**)&hB, g_hB);
    float* bufs[2] = { hA, hB };

    // layer 0
    lstm_gx0_kernel<<<TT, 256>>>(x, Wih[0], bih[0], bhh[0], gx);
    lstm_rec_kernel<<<BB / RROWS, 512>>>(gx, Whh[0], bufs[0]);

    // layers 1..4
    for (int l = 1; l < 5; l++) {
        const float* hin = bufs[(l - 1) & 1];
        float* ho = bufs[l & 1];
        lstm_gx_kernel<<<(TT * BB) / 64, 256>>>(hin, Wih[l], bih[l], bhh[l], gx);
        lstm_rec_kernel<<<BB / RROWS, 512>>>(gx, Whh[l], ho);
    }

    // linear head (layer 4 wrote bufs[0])
    lstm_lin_kernel<<<TT, 256>>>(bufs[0], Wl, bl, out);
}

// round 4
// speedup vs baseline: 1.0054x; 1.0054x over previous
#include <cuda_runtime.h>
#include <cstdint>

#define TT 512
#define BB 256
#define HH 64
#define GG 256     // 4*H
#define RROWS 2    // batch rows per recurrence CTA -> 128 CTAs

// Scratch (device globals; no allocation in kernel_launch)
__device__ float g_gx[(size_t)TT * BB * GG];   // [T][B][4H] permuted col order
__device__ float g_hA[(size_t)TT * BB * HH];   // [T][B][H]
__device__ float g_hB[(size_t)TT * BB * HH];

// ---- packed fp32x2 helpers (Blackwell FFMA2 via PTX) ----------------------
__device__ __forceinline__ unsigned long long ffma2(unsigned long long a,
                                                    unsigned long long b,
                                                    unsigned long long c) {
    unsigned long long d;
    asm("fma.rn.f32x2 %0, %1, %2, %3;" : "=l"(d) : "l"(a), "l"(b), "l"(c));
    return d;
}
__device__ __forceinline__ unsigned long long fadd2(unsigned long long a,
                                                    unsigned long long b) {
    unsigned long long d;
    asm("add.rn.f32x2 %0, %1, %2;" : "=l"(d) : "l"(a), "l"(b));
    return d;
}
__device__ __forceinline__ float2 unpack2(unsigned long long v) {
    float2 r;
    asm("mov.b64 {%0, %1}, %2;" : "=f"(r.x), "=f"(r.y) : "l"(v));
    return r;
}
// single-MUFU tanh (sm_75+)
__device__ __forceinline__ float tanh_approx(float x) {
    float y;
    asm("tanh.approx.f32 %0, %1;" : "=f"(y) : "f"(x));
    return y;
}

// gate index permutation: slot q <-> (j = q>>2, g = q&3), torch row = g*64+j
__device__ __forceinline__ int perm_row(int q) { return (q & 3) * 64 + (q >> 2); }

// ---------------------------------------------------------------------------
// Layer 0 input projection (d_in = 2), writes permuted gx layout.
// grid = T, block = 256
// ---------------------------------------------------------------------------
__global__ __launch_bounds__(256) void lstm_gx0_kernel(
    const float* __restrict__ x,      // [B][T][2]
    const float* __restrict__ Wih,    // [256][2]
    const float* __restrict__ bih,
    const float* __restrict__ bhh,
    float* __restrict__ gxout)        // [T][B][256] permuted
{
    __shared__ float xs[2 * BB];
    const int t = blockIdx.x;
    const int tid = threadIdx.x;
    const int wr = perm_row(tid);

    xs[2 * tid]     = x[((size_t)tid * TT + t) * 2 + 0];
    xs[2 * tid + 1] = x[((size_t)tid * TT + t) * 2 + 1];
    const float w0   = Wih[wr * 2];
    const float w1   = Wih[wr * 2 + 1];
    const float bias = bih[wr] + bhh[wr];
    __syncthreads();

    float* op = gxout + (size_t)t * BB * GG + tid;
#pragma unroll 4
    for (int r = 0; r < BB; r++) {
        op[r * GG] = fmaf(xs[2 * r], w0, fmaf(xs[2 * r + 1], w1, bias));
    }
}

// ---------------------------------------------------------------------------
// Layers 1..4 input projection: [T*B,64] x [64,256] + bias, FFMA2 packed.
// Writes permuted gx layout. 8-row accumulation blocks for ILP.
// grid = T*B/64, block = 256.
// ---------------------------------------------------------------------------
__global__ __launch_bounds__(256, 2) void lstm_gx_kernel(
    const float* __restrict__ xseq,   // [T][B][64]
    const float* __restrict__ Wih,    // [256][64]
    const float* __restrict__ bih,
    const float* __restrict__ bhh,
    float* __restrict__ gxout)        // [T][B][256] permuted
{
    __shared__ float4 xs4[64 * 16];   // 64 rows x 64 floats
    const int tid = threadIdx.x;
    const size_t base = (size_t)blockIdx.x * 64;
    const int wr = perm_row(tid);

    const float4* xin = reinterpret_cast<const float4*>(xseq + base * HH);
    for (int i = tid; i < 64 * 16; i += 256) xs4[i] = xin[i];

    // W row as 32 packed f32x2
    unsigned long long w[32];
    {
        const double2* wp = reinterpret_cast<const double2*>(Wih + wr * HH);
#pragma unroll
        for (int i = 0; i < 16; i++) {
            double2 d = wp[i];
            w[2 * i]     = __double_as_longlong(d.x);
            w[2 * i + 1] = __double_as_longlong(d.y);
        }
    }
    const float bias = bih[wr] + bhh[wr];
    __syncthreads();

    const double2* xsd = reinterpret_cast<const double2*>(xs4);
    float* op = gxout + base * GG + tid;
#pragma unroll 1
    for (int r0 = 0; r0 < 64; r0 += 8) {
        unsigned long long acc[8];
#pragma unroll
        for (int r = 0; r < 8; r++) acc[r] = 0ull;
#pragma unroll
        for (int i = 0; i < 16; i++) {
            const unsigned long long wl = w[2 * i], wh = w[2 * i + 1];
#pragma unroll
            for (int r = 0; r < 8; r++) {
                double2 xv = xsd[(r0 + r) * 16 + i];
                acc[r] = ffma2(wl, __double_as_longlong(xv.x), acc[r]);
                acc[r] = ffma2(wh, __double_as_longlong(xv.y), acc[r]);
            }
        }
#pragma unroll
        for (int r = 0; r < 8; r++) {
            float2 s = unpack2(acc[r]);
            op[(r0 + r) * GG] = bias + s.x + s.y;
        }
    }
}

// ---------------------------------------------------------------------------
// Recurrence: 512 threads, thread = (batch row r, hidden j, gate g).
// One 64-length packed dot per thread per step; single-MUFU activations
// (tanh.approx); quad shuffles gather gates; one barrier per step;
// h double-buffered in smem. grid = 128, block = 512.
// ---------------------------------------------------------------------------
__global__ __launch_bounds__(512, 1) void lstm_rec_kernel(
    const float* __restrict__ gx,     // [T][B][256] permuted
    const float* __restrict__ Whh,    // [256][64]
    float* __restrict__ hout)         // [T][B][64]
{
    __shared__ float h_s[2][RROWS * HH];
    const int tid = threadIdx.x;
    const int r = tid >> 8;           // batch row within CTA (0/1)
    const int q = tid & 255;          // gate slot
    const int j = q >> 2, g = q & 3;
    const int row0 = blockIdx.x * RROWS;
    const int wr = g * 64 + j;        // torch gate row

    // W_hh row as 32 packed f32x2
    unsigned long long w[32];
    {
        const double2* wp = reinterpret_cast<const double2*>(Whh + wr * HH);
#pragma unroll
        for (int i = 0; i < 16; i++) {
            double2 d = wp[i];
            w[2 * i]     = __double_as_longlong(d.x);
            w[2 * i + 1] = __double_as_longlong(d.y);
        }
    }

    float c = 0.0f;
    if (tid < RROWS * HH) h_s[0][tid] = 0.0f;
    __syncthreads();

    float gxv = gx[((size_t)0 * BB + row0 + r) * GG + q];

    // activation constants: sigmoid (g != 2): act = 0.5*tanh(0.5 v) + 0.5
    //                       tanh    (g == 2): act = 1.0*tanh(1.0 v) + 0.0
    const float sc2 = (g == 2) ? 1.0f : 0.5f;
    const float Am  = (g == 2) ? 1.0f : 0.5f;
    const float Bc  = (g == 2) ? 0.0f : 0.5f;

    for (int t = 0; t < TT; t++) {
        const int p = t & 1;
        // prefetch next gx (consumed after the barrier)
        float nx = 0.0f;
        if (t + 1 < TT)
            nx = __ldg(&gx[((size_t)(t + 1) * BB + row0 + r) * GG + q]);

        // packed dot: gate = gx + W_row . h(r)
        unsigned long long a = 0ull, b = 0ull;
        const double2* hp = reinterpret_cast<const double2*>(h_s[p] + r * HH);
#pragma unroll
        for (int i = 0; i < 16; i++) {
            double2 hv = hp[i];
            a = ffma2(w[2 * i],     __double_as_longlong(hv.x), a);
            b = ffma2(w[2 * i + 1], __double_as_longlong(hv.y), b);
        }
        float2 s = unpack2(fadd2(a, b));
        const float v = gxv + s.x + s.y;

        // single-MUFU activation
        const float act = fmaf(tanh_approx(v * sc2), Am, Bc);

        // quad gather (gates i,f,g,o live in lanes 0..3 of each quad)
        const unsigned m = 0xffffffffu;
        const float ig = __shfl_sync(m, act, 0, 4);
        const float fg = __shfl_sync(m, act, 1, 4);
        const float Gg = __shfl_sync(m, act, 2, 4);
        const float og = __shfl_sync(m, act, 3, 4);

        c = fmaf(fg, c, ig * Gg);
        const float hv = og * tanh_approx(c);

        if (g == 0) {
            h_s[p ^ 1][r * HH + j] = hv;
            hout[((size_t)t * BB + row0 + r) * HH + j] = hv;
        }
        __syncthreads();   // the ONLY barrier per step
        gxv = nx;
    }
}

// ---------------------------------------------------------------------------
// Final linear head. grid = T, block = 256.
// ---------------------------------------------------------------------------
__global__ __launch_bounds__(256) void lstm_lin_kernel(
    const float* __restrict__ hseq,   // [T][B][64]
    const float* __restrict__ Wl,     // [64]
    const float* __restrict__ bl,     // [1]
    float* __restrict__ out)          // [B][T]
{
    __shared__ float4 wl4[16];
    const int t = blockIdx.x;
    const int b = threadIdx.x;
    if (threadIdx.x < 16)
        wl4[threadIdx.x] = reinterpret_cast<const float4*>(Wl)[threadIdx.x];
    __syncthreads();

    const float4* hp = reinterpret_cast<const float4*>(hseq + ((size_t)t * BB + b) * HH);
    float acc = bl[0];
#pragma unroll
    for (int k4 = 0; k4 < 16; k4++) {
        const float4 h = hp[k4];
        const float4 w = wl4[k4];
        acc = fmaf(h.x, w.x, acc);
        acc = fmaf(h.y, w.y, acc);
        acc = fmaf(h.z, w.z, acc);
        acc = fmaf(h.w, w.w, acc);
    }
    out[(size_t)b * TT + t] = acc;
}

// ---------------------------------------------------------------------------
extern "C" void kernel_launch(void* const* d_in, const int* in_sizes, int n_in,
                              void* d_out, int out_size)
{
    (void)in_sizes; (void)n_in; (void)out_size;

    const float* x = (const float*)d_in[0];
    const float* Wih[5]; const float* Whh[5]; const float* bih[5]; const float* bhh[5];
    for (int l = 0; l < 5; l++) {
        Wih[l] = (const float*)d_in[1 + 4 * l];
        Whh[l] = (const float*)d_in[2 + 4 * l];
        bih[l] = (const float*)d_in[3 + 4 * l];
        bhh[l] = (const float*)d_in[4 + 4 * l];
    }
    const float* Wl = (const float*)d_in[21];
    const float* bl = (const float*)d_in[22];
    float* out = (float*)d_out;

    float *gx, *hA, *hB;
    cudaGetSymbolAddress((void**)&gx, g_gx);
    cudaGetSymbolAddress((void**)&hA, g_hA);
    cudaGetSymbolAddress((void**)&hB, g_hB);
    float* bufs[2] = { hA, hB };

    // layer 0
    lstm_gx0_kernel<<<TT, 256>>>(x, Wih[0], bih[0], bhh[0], gx);
    lstm_rec_kernel<<<BB / RROWS, 512>>>(gx, Whh[0], bufs[0]);

    // layers 1..4
    for (int l = 1; l < 5; l++) {
        const float* hin = bufs[(l - 1) & 1];
        float* ho = bufs[l & 1];
        lstm_gx_kernel<<<(TT * BB) / 64, 256>>>(hin, Wih[l], bih[l], bhh[l], gx);
        lstm_rec_kernel<<<BB / RROWS, 512>>>(gx, Whh[l], ho);
    }

    // linear head (layer 4 wrote bufs[0])
    lstm_lin_kernel<<<TT, 256>>>(bufs[0], Wl, bl, out);
}

// round 7
// speedup vs baseline: 1.3136x; 1.3066x over previous
#include <cuda_runtime.h>
#include <cstdint>

#define TT 512
#define BB 256
#define HH 64
#define GG 256     // 4*H
#define RROWS 2    // batch rows per recurrence CTA -> 128 CTAs
#define PF 8       // gx prefetch depth (steps ahead); keep unroll pragma in sync
static_assert(PF == 8, "update '#pragma unroll 8' in lstm_rec_kernel if PF changes");

// Scratch (device globals; no allocation in kernel_launch)
__device__ float g_gx[(size_t)TT * BB * GG];   // [T][B][4H] permuted col order
__device__ float g_hA[(size_t)TT * BB * HH];   // [T][B][H]
__device__ float g_hB[(size_t)TT * BB * HH];

// ---- packed fp32x2 helpers (Blackwell FFMA2 via PTX) ----------------------
__device__ __forceinline__ unsigned long long ffma2(unsigned long long a,
                                                    unsigned long long b,
                                                    unsigned long long c) {
    unsigned long long d;
    asm("fma.rn.f32x2 %0, %1, %2, %3;" : "=l"(d) : "l"(a), "l"(b), "l"(c));
    return d;
}
__device__ __forceinline__ unsigned long long fadd2(unsigned long long a,
                                                    unsigned long long b) {
    unsigned long long d;
    asm("add.rn.f32x2 %0, %1, %2;" : "=l"(d) : "l"(a), "l"(b));
    return d;
}
__device__ __forceinline__ float2 unpack2(unsigned long long v) {
    float2 r;
    asm("mov.b64 {%0, %1}, %2;" : "=f"(r.x), "=f"(r.y) : "l"(v));
    return r;
}
// single-MUFU tanh (sm_75+)
__device__ __forceinline__ float tanh_approx(float x) {
    float y;
    asm("tanh.approx.f32 %0, %1;" : "=f"(y) : "f"(x));
    return y;
}

// gate index permutation: slot q <-> (j = q>>2, g = q&3), torch row = g*64+j
__device__ __forceinline__ int perm_row(int q) { return (q & 3) * 64 + (q >> 2); }

// ---------------------------------------------------------------------------
// Layer 0 input projection (d_in = 2), writes permuted gx layout.
// grid = T, block = 256
// ---------------------------------------------------------------------------
__global__ __launch_bounds__(256) void lstm_gx0_kernel(
    const float* __restrict__ x,      // [B][T][2]
    const float* __restrict__ Wih,    // [256][2]
    const float* __restrict__ bih,
    const float* __restrict__ bhh,
    float* __restrict__ gxout)        // [T][B][256] permuted
{
    __shared__ float xs[2 * BB];
    const int t = blockIdx.x;
    const int tid = threadIdx.x;
    const int wr = perm_row(tid);

    xs[2 * tid]     = x[((size_t)tid * TT + t) * 2 + 0];
    xs[2 * tid + 1] = x[((size_t)tid * TT + t) * 2 + 1];
    const float w0   = Wih[wr * 2];
    const float w1   = Wih[wr * 2 + 1];
    const float bias = bih[wr] + bhh[wr];
    __syncthreads();

    float* op = gxout + (size_t)t * BB * GG + tid;
#pragma unroll 4
    for (int r = 0; r < BB; r++) {
        op[r * GG] = fmaf(xs[2 * r], w0, fmaf(xs[2 * r + 1], w1, bias));
    }
}

// ---------------------------------------------------------------------------
// Layers 1..4 input projection: [T*B,64] x [64,256] + bias, FFMA2 packed.
// Writes permuted gx layout. 8-row accumulation blocks for ILP.
// grid = T*B/64, block = 256.
// ---------------------------------------------------------------------------
__global__ __launch_bounds__(256, 2) void lstm_gx_kernel(
    const float* __restrict__ xseq,   // [T][B][64]
    const float* __restrict__ Wih,    // [256][64]
    const float* __restrict__ bih,
    const float* __restrict__ bhh,
    float* __restrict__ gxout)        // [T][B][256] permuted
{
    __shared__ float4 xs4[64 * 16];   // 64 rows x 64 floats
    const int tid = threadIdx.x;
    const size_t base = (size_t)blockIdx.x * 64;
    const int wr = perm_row(tid);

    const float4* xin = reinterpret_cast<const float4*>(xseq + base * HH);
    for (int i = tid; i < 64 * 16; i += 256) xs4[i] = xin[i];

    // W row as 32 packed f32x2
    unsigned long long w[32];
    {
        const double2* wp = reinterpret_cast<const double2*>(Wih + wr * HH);
#pragma unroll
        for (int i = 0; i < 16; i++) {
            double2 d = wp[i];
            w[2 * i]     = __double_as_longlong(d.x);
            w[2 * i + 1] = __double_as_longlong(d.y);
        }
    }
    const float bias = bih[wr] + bhh[wr];
    __syncthreads();

    const double2* xsd = reinterpret_cast<const double2*>(xs4);
    float* op = gxout + base * GG + tid;
#pragma unroll 1
    for (int r0 = 0; r0 < 64; r0 += 8) {
        unsigned long long acc[8];
#pragma unroll
        for (int r = 0; r < 8; r++) acc[r] = 0ull;
#pragma unroll
        for (int i = 0; i < 16; i++) {
            const unsigned long long wl = w[2 * i], wh = w[2 * i + 1];
#pragma unroll
            for (int r = 0; r < 8; r++) {
                double2 xv = xsd[(r0 + r) * 16 + i];
                acc[r] = ffma2(wl, __double_as_longlong(xv.x), acc[r]);
                acc[r] = ffma2(wh, __double_as_longlong(xv.y), acc[r]);
            }
        }
#pragma unroll
        for (int r = 0; r < 8; r++) {
            float2 s = unpack2(acc[r]);
            op[(r0 + r) * GG] = bias + s.x + s.y;
        }
    }
}

// ---------------------------------------------------------------------------
// Recurrence: 512 threads, thread = (batch row r, hidden j, gate g).
// 8-deep gx prefetch ring (MLP=8) hides DRAM latency; one packed 64-dot per
// thread per step; tanh.approx activations; quad shuffles; one barrier/step.
// grid = 128, block = 512.
// ---------------------------------------------------------------------------
__global__ __launch_bounds__(512, 1) void lstm_rec_kernel(
    const float* __restrict__ gx,     // [T][B][256] permuted
    const float* __restrict__ Whh,    // [256][64]
    float* __restrict__ hout)         // [T][B][64]
{
    __shared__ float h_s[2][RROWS * HH];
    const int tid = threadIdx.x;
    const int r = tid >> 8;           // batch row within CTA (0/1)
    const int q = tid & 255;          // gate slot
    const int j = q >> 2, g = q & 3;
    const int row0 = blockIdx.x * RROWS;
    const int wr = g * 64 + j;        // torch gate row

    // W_hh row as 32 packed f32x2
    unsigned long long w[32];
    {
        const double2* wp = reinterpret_cast<const double2*>(Whh + wr * HH);
#pragma unroll
        for (int i = 0; i < 16; i++) {
            double2 d = wp[i];
            w[2 * i]     = __double_as_longlong(d.x);
            w[2 * i + 1] = __double_as_longlong(d.y);
        }
    }

    const float* gxp = gx + (size_t)(row0 + r) * GG + q;   // + t*BB*GG per step

    float c = 0.0f;
    if (tid < RROWS * HH) h_s[0][tid] = 0.0f;
    __syncthreads();

    // prefetch ring: slot i holds gx for step (t : t % PF == i), PF ahead
    float gring[PF];
#pragma unroll
    for (int i = 0; i < PF; i++)
        gring[i] = __ldg(gxp + (size_t)i * BB * GG);

    // activation constants: sigmoid (g != 2): act = 0.5*tanh(0.5 v) + 0.5
    //                       tanh    (g == 2): act = 1.0*tanh(1.0 v) + 0.0
    const float sc2 = (g == 2) ? 1.0f : 0.5f;
    const float Am  = (g == 2) ? 1.0f : 0.5f;
    const float Bc  = (g == 2) ? 0.0f : 0.5f;

#pragma unroll 8
    for (int t = 0; t < TT; t++) {
        const int p = t & 1;
        const int slot = t & (PF - 1);
        const float gxv = gring[slot];
        // refill slot with step t+PF (slack = PF steps, MLP = PF)
        if (t + PF < TT)
            gring[slot] = __ldg(gxp + (size_t)(t + PF) * BB * GG);

        // packed dot: gate = gx + W_row . h(r)
        unsigned long long a = 0ull, b = 0ull;
        const double2* hp = reinterpret_cast<const double2*>(h_s[p] + r * HH);
#pragma unroll
        for (int i = 0; i < 16; i++) {
            double2 hv = hp[i];
            a = ffma2(w[2 * i],     __double_as_longlong(hv.x), a);
            b = ffma2(w[2 * i + 1], __double_as_longlong(hv.y), b);
        }
        float2 s = unpack2(fadd2(a, b));
        const float v = gxv + s.x + s.y;

        // single-MUFU activation
        const float act = fmaf(tanh_approx(v * sc2), Am, Bc);

        // quad gather (gates i,f,g,o live in lanes 0..3 of each quad)
        const unsigned m = 0xffffffffu;
        const float ig = __shfl_sync(m, act, 0, 4);
        const float fg = __shfl_sync(m, act, 1, 4);
        const float Gg = __shfl_sync(m, act, 2, 4);
        const float og = __shfl_sync(m, act, 3, 4);

        c = fmaf(fg, c, ig * Gg);
        const float hv = og * tanh_approx(c);

        if (g == 0) {
            h_s[p ^ 1][r * HH + j] = hv;
            hout[((size_t)t * BB + row0 + r) * HH + j] = hv;
        }
        __syncthreads();   // the ONLY barrier per step
    }
}

// ---------------------------------------------------------------------------
// Final linear head. grid = T, block = 256.
// ---------------------------------------------------------------------------
__global__ __launch_bounds__(256) void lstm_lin_kernel(
    const float* __restrict__ hseq,   // [T][B][64]
    const float* __restrict__ Wl,     // [64]
    const float* __restrict__ bl,     // [1]
    float* __restrict__ out)          // [B][T]
{
    __shared__ float4 wl4[16];
    const int t = blockIdx.x;
    const int b = threadIdx.x;
    if (threadIdx.x < 16)
        wl4[threadIdx.x] = reinterpret_cast<const float4*>(Wl)[threadIdx.x];
    __syncthreads();

    const float4* hp = reinterpret_cast<const float4*>(hseq + ((size_t)t * BB + b) * HH);
    float acc = bl[0];
#pragma unroll
    for (int k4 = 0; k4 < 16; k4++) {
        const float4 h = hp[k4];
        const float4 w = wl4[k4];
        acc = fmaf(h.x, w.x, acc);
        acc = fmaf(h.y, w.y, acc);
        acc = fmaf(h.z, w.z, acc);
        acc = fmaf(h.w, w.w, acc);
    }
    out[(size_t)b * TT + t] = acc;
}

// ---------------------------------------------------------------------------
extern "C" void kernel_launch(void* const* d_in, const int* in_sizes, int n_in,
                              void* d_out, int out_size)
{
    (void)in_sizes; (void)n_in; (void)out_size;

    const float* x = (const float*)d_in[0];
    const float* Wih[5]; const float* Whh[5]; const float* bih[5]; const float* bhh[5];
    for (int l = 0; l < 5; l++) {
        Wih[l] = (const float*)d_in[1 + 4 * l];
        Whh[l] = (const float*)d_in[2 + 4 * l];
        bih[l] = (const float*)d_in[3 + 4 * l];
        bhh[l] = (const float*)d_in[4 + 4 * l];
    }
    const float* Wl = (const float*)d_in[21];
    const float* bl = (const float*)d_in[22];
    float* out = (float*)d_out;

    float *gx, *hA, *hB;
    cudaGetSymbolAddress((void**)&gx, g_gx);
    cudaGetSymbolAddress((void**)&hA, g_hA);
    cudaGetSymbolAddress((void**)&hB, g_hB);
    float* bufs[2] = { hA, hB };

    // layer 0
    lstm_gx0_kernel<<<TT, 256>>>(x, Wih[0], bih[0], bhh[0], gx);
    lstm_rec_kernel<<<BB / RROWS, 512>>>(gx, Whh[0], bufs[0]);

    // layers 1..4
    for (int l = 1; l < 5; l++) {
        const float* hin = bufs[(l - 1) & 1];
        float* ho = bufs[l & 1];
        lstm_gx_kernel<<<(TT * BB) / 64, 256>>>(hin, Wih[l], bih[l], bhh[l], gx);
        lstm_rec_kernel<<<BB / RROWS, 512>>>(gx, Whh[l], ho);
    }

    // linear head (layer 4 wrote bufs[0])
    lstm_lin_kernel<<<TT, 256>>>(bufs[0], Wl, bl, out);
}

// round 9
// speedup vs baseline: 1.3444x; 1.0235x over previous
#include <cuda_runtime.h>
#include <cstdint>

#define TT 512
#define BB 256
#define HH 64
#define GG 256     // 4*H
#define RROWS 2    // batch rows per recurrence CTA -> 128 CTAs
#define PF 8       // gx prefetch depth (steps ahead); keep unroll pragma in sync
#define GXR 32     // batch-time rows per gx CTA
#define KPH 32     // K per smem phase in gx
static_assert(PF == 8, "update '#pragma unroll 8' in lstm_rec_kernel if PF changes");

// Scratch (device globals; no allocation in kernel_launch)
__device__ float g_gx[(size_t)TT * BB * GG];   // [T][B][4H] permuted col order
__device__ float g_hA[(size_t)TT * BB * HH];   // [T][B][H]
__device__ float g_hB[(size_t)TT * BB * HH];

// ---- packed fp32x2 helpers (Blackwell FFMA2 via PTX) ----------------------
__device__ __forceinline__ unsigned long long ffma2(unsigned long long a,
                                                    unsigned long long b,
                                                    unsigned long long c) {
    unsigned long long d;
    asm("fma.rn.f32x2 %0, %1, %2, %3;" : "=l"(d) : "l"(a), "l"(b), "l"(c));
    return d;
}
__device__ __forceinline__ unsigned long long fadd2(unsigned long long a,
                                                    unsigned long long b) {
    unsigned long long d;
    asm("add.rn.f32x2 %0, %1, %2;" : "=l"(d) : "l"(a), "l"(b));
    return d;
}
__device__ __forceinline__ float2 unpack2(unsigned long long v) {
    float2 r;
    asm("mov.b64 {%0, %1}, %2;" : "=f"(r.x), "=f"(r.y) : "l"(v));
    return r;
}
__device__ __forceinline__ unsigned long long pack2(float lo, float hi) {
    unsigned long long d;
    asm("mov.b64 %0, {%1, %2};" : "=l"(d) : "f"(lo), "f"(hi));
    return d;
}
// single-MUFU tanh (sm_75+)
__device__ __forceinline__ float tanh_approx(float x) {
    float y;
    asm("tanh.approx.f32 %0, %1;" : "=f"(y) : "f"(x));
    return y;
}

// gate index permutation: slot q <-> (j = q>>2, g = q&3), torch row = g*64+j
__device__ __forceinline__ int perm_row(int q) { return (q & 3) * 64 + (q >> 2); }

// ---------------------------------------------------------------------------
// Layer 0 input projection (d_in = 2), writes permuted gx layout.
// grid = T, block = 256
// ---------------------------------------------------------------------------
__global__ __launch_bounds__(256) void lstm_gx0_kernel(
    const float* __restrict__ x,      // [B][T][2]
    const float* __restrict__ Wih,    // [256][2]
    const float* __restrict__ bih,
    const float* __restrict__ bhh,
    float* __restrict__ gxout)        // [T][B][256] permuted
{
    __shared__ float xs[2 * BB];
    const int t = blockIdx.x;
    const int tid = threadIdx.x;
    const int wr = perm_row(tid);

    xs[2 * tid]     = x[((size_t)tid * TT + t) * 2 + 0];
    xs[2 * tid + 1] = x[((size_t)tid * TT + t) * 2 + 1];
    const float w0   = Wih[wr * 2];
    const float w1   = Wih[wr * 2 + 1];
    const float bias = bih[wr] + bhh[wr];
    __syncthreads();

    float* op = gxout + (size_t)t * BB * GG + tid;
#pragma unroll 4
    for (int r = 0; r < BB; r++) {
        op[r * GG] = fmaf(xs[2 * r], w0, fmaf(xs[2 * r + 1], w1, bias));
    }
}

// ---------------------------------------------------------------------------
// Layers 1..4 input projection: register-tiled GEMM [T*B,64] x [64,256].
// CTA tile: 32 rows x 256 gates; thread tile: 8 rows x 4 gates.
// W transposed k-major in smem (Wt[k][slot]): one LDS.128 = 4 gate weights,
// packed over gates for FFMA2. x broadcast from smem. K in 2 phases of 32.
// grid = T*B/32, block = 256.
// ---------------------------------------------------------------------------
__global__ __launch_bounds__(256, 2) void lstm_gx_kernel(
    const float* __restrict__ xseq,   // [T][B][64]
    const float* __restrict__ Wih,    // [256][64]
    const float* __restrict__ bih,
    const float* __restrict__ bhh,
    float* __restrict__ gxout)        // [T][B][256] permuted
{
    __shared__ float Wt[KPH][GG];                 // 32KB, [k][slot]
    __shared__ __align__(16) float xs[GXR][36];   // padded rows (bank spread)
    __shared__ float bs[GG];

    const int tid = threadIdx.x;
    const size_t base = (size_t)blockIdx.x * GXR;
    const int gc = tid & 63;          // gate group: slots 4gc..4gc+3
    const int rq = tid >> 6;          // row group: rows 8rq..8rq+7
    const int s  = tid;               // slot this thread loads W for
    const int wr = (s & 3) * 64 + (s >> 2);   // torch row of slot s

    bs[s] = bih[wr] + bhh[wr];

    unsigned long long acc[8][2];
#pragma unroll
    for (int r = 0; r < 8; r++) { acc[r][0] = 0ull; acc[r][1] = 0ull; }

#pragma unroll 1
    for (int ph = 0; ph < 2; ph++) {
        const int k0 = ph * KPH;
        if (ph) __syncthreads();      // all reads of previous phase done
        // W phase load: Wih[wr][k0..k0+32] -> Wt[k][s]  (STS conflict-free)
        {
            const float4* wp = reinterpret_cast<const float4*>(
                Wih + (size_t)wr * HH + k0);
#pragma unroll
            for (int i = 0; i < KPH / 4; i++) {
                float4 v = wp[i];
                Wt[4 * i + 0][s] = v.x;
                Wt[4 * i + 1][s] = v.y;
                Wt[4 * i + 2][s] = v.z;
                Wt[4 * i + 3][s] = v.w;
            }
        }
        // x phase load: 32 rows x 32 k, one float4 per thread
        {
            const int row = tid >> 3, c4 = (tid & 7) * 4;
            const float4 v = *reinterpret_cast<const float4*>(
                xseq + (base + row) * HH + k0 + c4);
            *reinterpret_cast<float4*>(&xs[row][c4]) = v;
        }
        __syncthreads();

#pragma unroll
        for (int k4 = 0; k4 < KPH / 4; k4++) {
            float4 xv[8];
#pragma unroll
            for (int r = 0; r < 8; r++)
                xv[r] = *reinterpret_cast<const float4*>(&xs[rq * 8 + r][k4 * 4]);
#pragma unroll
            for (int kk = 0; kk < 4; kk++) {
                const float4 wv = *reinterpret_cast<const float4*>(
                    &Wt[k4 * 4 + kk][4 * gc]);
                const unsigned long long w01 = pack2(wv.x, wv.y);
                const unsigned long long w23 = pack2(wv.z, wv.w);
#pragma unroll
                for (int r = 0; r < 8; r++) {
                    const float xr = (&xv[r].x)[kk];
                    const unsigned long long xx = pack2(xr, xr);
                    acc[r][0] = ffma2(w01, xx, acc[r][0]);
                    acc[r][1] = ffma2(w23, xx, acc[r][1]);
                }
            }
        }
    }

    const float4 bv = *reinterpret_cast<const float4*>(&bs[4 * gc]);
#pragma unroll
    for (int r = 0; r < 8; r++) {
        float2 a = unpack2(acc[r][0]);
        float2 b = unpack2(acc[r][1]);
        float4 o = make_float4(bv.x + a.x, bv.y + a.y, bv.z + b.x, bv.w + b.y);
        *reinterpret_cast<float4*>(
            &gxout[(base + rq * 8 + r) * GG + 4 * gc]) = o;
    }
}

// ---------------------------------------------------------------------------
// Recurrence: 512 threads, thread = (batch row r, hidden j, gate g).
// The two batch rows are independent recurrences: each row's 8 warps sync
// on their OWN named barrier, so the rows drift and fill each other's
// pipeline stalls. 8-deep gx prefetch ring (MLP=8); packed FFMA2 dots;
// tanh.approx; quad shuffles. grid = 128, block = 512.
// ---------------------------------------------------------------------------
__global__ __launch_bounds__(512, 1) void lstm_rec_kernel(
    const float* __restrict__ gx,     // [T][B][256] permuted
    const float* __restrict__ Whh,    // [256][64]
    float* __restrict__ hout)         // [T][B][64]
{
    __shared__ __align__(16) float h_s[2][RROWS * HH];
    const int tid = threadIdx.x;
    const int r = tid >> 8;           // batch row within CTA (0/1)
    const int q = tid & 255;          // gate slot
    const int j = q >> 2, g = q & 3;
    const int row0 = blockIdx.x * RROWS;
    const int wr = g * 64 + j;        // torch gate row
    const int barid = 1 + r;          // per-row named barrier

    // W_hh row as 32 packed f32x2
    unsigned long long w[32];
    {
        const double2* wp = reinterpret_cast<const double2*>(Whh + wr * HH);
#pragma unroll
        for (int i = 0; i < 16; i++) {
            double2 d = wp[i];
            w[2 * i]     = __double_as_longlong(d.x);
            w[2 * i + 1] = __double_as_longlong(d.y);
        }
    }

    const float* gxp = gx + (size_t)(row0 + r) * GG + q;   // + t*BB*GG per step

    float c = 0.0f;
    if (tid < RROWS * HH) h_s[0][tid] = 0.0f;
    __syncthreads();

    // prefetch ring: slot i holds gx for step (t : t % PF == i), PF ahead
    float gring[PF];
#pragma unroll
    for (int i = 0; i < PF; i++)
        gring[i] = __ldg(gxp + (size_t)i * BB * GG);

    // activation constants: sigmoid (g != 2): act = 0.5*tanh(0.5 v) + 0.5
    //                       tanh    (g == 2): act = 1.0*tanh(1.0 v) + 0.0
    const float sc2 = (g == 2) ? 1.0f : 0.5f;
    const float Am  = (g == 2) ? 1.0f : 0.5f;
    const float Bc  = (g == 2) ? 0.0f : 0.5f;

#pragma unroll 8
    for (int t = 0; t < TT; t++) {
        const int p = t & 1;
        const int slot = t & (PF - 1);
        const float gxv = gring[slot];
        // refill slot with step t+PF (slack = PF steps, MLP = PF)
        if (t + PF < TT)
            gring[slot] = __ldg(gxp + (size_t)(t + PF) * BB * GG);

        // packed dot: gate = gx + W_row . h(r)
        unsigned long long a = 0ull, b = 0ull;
        const double2* hp = reinterpret_cast<const double2*>(h_s[p] + r * HH);
#pragma unroll
        for (int i = 0; i < 16; i++) {
            double2 hv = hp[i];
            a = ffma2(w[2 * i],     __double_as_longlong(hv.x), a);
            b = ffma2(w[2 * i + 1], __double_as_longlong(hv.y), b);
        }
        float2 s = unpack2(fadd2(a, b));
        const float v = gxv + s.x + s.y;

        // single-MUFU activation
        const float act = fmaf(tanh_approx(v * sc2), Am, Bc);

        // quad gather (gates i,f,g,o live in lanes 0..3 of each quad)
        const unsigned m = 0xffffffffu;
        const float ig = __shfl_sync(m, act, 0, 4);
        const float fg = __shfl_sync(m, act, 1, 4);
        const float Gg = __shfl_sync(m, act, 2, 4);
        const float og = __shfl_sync(m, act, 3, 4);

        c = fmaf(fg, c, ig * Gg);
        const float hv = og * tanh_approx(c);

        if (g == 0) {
            h_s[p ^ 1][r * HH + j] = hv;
            hout[((size_t)t * BB + row0 + r) * HH + j] = hv;
        }
        // per-row named barrier: only this row's 8 warps (256 threads)
        asm volatile("bar.sync %0, %1;" :: "r"(barid), "r"(256) : "memory");
    }
}

// ---------------------------------------------------------------------------
// Final linear head. grid = T, block = 256.
// ---------------------------------------------------------------------------
__global__ __launch_bounds__(256) void lstm_lin_kernel(
    const float* __restrict__ hseq,   // [T][B][64]
    const float* __restrict__ Wl,     // [64]
    const float* __restrict__ bl,     // [1]
    float* __restrict__ out)          // [B][T]
{
    __shared__ float4 wl4[16];
    const int t = blockIdx.x;
    const int b = threadIdx.x;
    if (threadIdx.x < 16)
        wl4[threadIdx.x] = reinterpret_cast<const float4*>(Wl)[threadIdx.x];
    __syncthreads();

    const float4* hp = reinterpret_cast<const float4*>(hseq + ((size_t)t * BB + b) * HH);
    float acc = bl[0];
#pragma unroll
    for (int k4 = 0; k4 < 16; k4++) {
        const float4 h = hp[k4];
        const float4 w = wl4[k4];
        acc = fmaf(h.x, w.x, acc);
        acc = fmaf(h.y, w.y, acc);
        acc = fmaf(h.z, w.z, acc);
        acc = fmaf(h.w, w.w, acc);
    }
    out[(size_t)b * TT + t] = acc;
}

// ---------------------------------------------------------------------------
extern "C" void kernel_launch(void* const* d_in, const int* in_sizes, int n_in,
                              void* d_out, int out_size)
{
    (void)in_sizes; (void)n_in; (void)out_size;

    const float* x = (const float*)d_in[0];
    const float* Wih[5]; const float* Whh[5]; const float* bih[5]; const float* bhh[5];
    for (int l = 0; l < 5; l++) {
        Wih[l] = (const float*)d_in[1 + 4 * l];
        Whh[l] = (const float*)d_in[2 + 4 * l];
        bih[l] = (const float*)d_in[3 + 4 * l];
        bhh[l] = (const float*)d_in[4 + 4 * l];
    }
    const float* Wl = (const float*)d_in[21];
    const float* bl = (const float*)d_in[22];
    float* out = (float*)d_out;

    float *gx, *hA, *hB;
    cudaGetSymbolAddress((void**)&gx, g_gx);
    cudaGetSymbolAddress((void**)&hA, g_hA);
    cudaGetSymbolAddress((void**)&hB, g_hB);
    float* bufs[2] = { hA, hB };

    // layer 0
    lstm_gx0_kernel<<<TT, 256>>>(x, Wih[0], bih[0], bhh[0], gx);
    lstm_rec_kernel<<<BB / RROWS, 512>>>(gx, Whh[0], bufs[0]);

    // layers 1..4
    for (int l = 1; l < 5; l++) {
        const float* hin = bufs[(l - 1) & 1];
        float* ho = bufs[l & 1];
        lstm_gx_kernel<<<(TT * BB) / GXR, 256>>>(hin, Wih[l], bih[l], bhh[l], gx);
        lstm_rec_kernel<<<BB / RROWS, 512>>>(gx, Whh[l], ho);
    }

    // linear head (layer 4 wrote bufs[0])
    lstm_lin_kernel<<<TT, 256>>>(bufs[0], Wl, bl, out);
}

// round 10
// speedup vs baseline: 1.5312x; 1.1389x over previous
#include <cuda_runtime.h>
#include <cstdint>

#define TT 512
#define BB 256
#define HH 64
#define GG 256     // 4*H
#define RROWS 2    // batch rows per recurrence CTA -> 128 CTAs
#define PF 8       // gx prefetch depth (steps ahead); keep unroll pragma in sync
#define GXR 32     // batch-time rows per gx CTA
#define KPH 32     // K per smem phase in gx
static_assert(PF == 8, "update '#pragma unroll 8' in lstm_rec_kernel if PF changes");

// Scratch (device globals; no allocation in kernel_launch)
__device__ float g_gx[(size_t)TT * BB * GG];   // [T][B][4H] permuted col order
__device__ float g_hA[(size_t)TT * BB * HH];   // [T][B][H]
__device__ float g_hB[(size_t)TT * BB * HH];

// ---- packed fp32x2 helpers (Blackwell FFMA2 via PTX) ----------------------
__device__ __forceinline__ unsigned long long ffma2(unsigned long long a,
                                                    unsigned long long b,
                                                    unsigned long long c) {
    unsigned long long d;
    asm("fma.rn.f32x2 %0, %1, %2, %3;" : "=l"(d) : "l"(a), "l"(b), "l"(c));
    return d;
}
__device__ __forceinline__ unsigned long long fadd2(unsigned long long a,
                                                    unsigned long long b) {
    unsigned long long d;
    asm("add.rn.f32x2 %0, %1, %2;" : "=l"(d) : "l"(a), "l"(b));
    return d;
}
__device__ __forceinline__ float2 unpack2(unsigned long long v) {
    float2 r;
    asm("mov.b64 {%0, %1}, %2;" : "=f"(r.x), "=f"(r.y) : "l"(v));
    return r;
}
__device__ __forceinline__ unsigned long long pack2(float lo, float hi) {
    unsigned long long d;
    asm("mov.b64 %0, {%1, %2};" : "=l"(d) : "f"(lo), "f"(hi));
    return d;
}
// single-MUFU tanh (sm_75+)
__device__ __forceinline__ float tanh_approx(float x) {
    float y;
    asm("tanh.approx.f32 %0, %1;" : "=f"(y) : "f"(x));
    return y;
}

// gate index permutation: slot q <-> (j = q>>2, g = q&3), torch row = g*64+j
__device__ __forceinline__ int perm_row(int q) { return (q & 3) * 64 + (q >> 2); }

// ---------------------------------------------------------------------------
// Layer 0 input projection (d_in = 2), writes permuted gx layout.
// grid = T, block = 256
// ---------------------------------------------------------------------------
__global__ __launch_bounds__(256) void lstm_gx0_kernel(
    const float* __restrict__ x,      // [B][T][2]
    const float* __restrict__ Wih,    // [256][2]
    const float* __restrict__ bih,
    const float* __restrict__ bhh,
    float* __restrict__ gxout)        // [T][B][256] permuted
{
    __shared__ float xs[2 * BB];
    const int t = blockIdx.x;
    const int tid = threadIdx.x;
    const int wr = perm_row(tid);

    xs[2 * tid]     = x[((size_t)tid * TT + t) * 2 + 0];
    xs[2 * tid + 1] = x[((size_t)tid * TT + t) * 2 + 1];
    const float w0   = Wih[wr * 2];
    const float w1   = Wih[wr * 2 + 1];
    const float bias = bih[wr] + bhh[wr];
    __syncthreads();

    float* op = gxout + (size_t)t * BB * GG + tid;
#pragma unroll 4
    for (int r = 0; r < BB; r++) {
        op[r * GG] = fmaf(xs[2 * r], w0, fmaf(xs[2 * r + 1], w1, bias));
    }
}

// ---------------------------------------------------------------------------
// Layers 1..4 input projection: register-tiled GEMM [T*B,64] x [64,256].
// CTA tile: 32 rows x 256 gates; thread tile: 8 rows x 4 gates.
// W transposed k-major in smem; x broadcast; K in 2 phases of 32.
// grid = T*B/32, block = 256.
// ---------------------------------------------------------------------------
__global__ __launch_bounds__(256, 2) void lstm_gx_kernel(
    const float* __restrict__ xseq,   // [T][B][64]
    const float* __restrict__ Wih,    // [256][64]
    const float* __restrict__ bih,
    const float* __restrict__ bhh,
    float* __restrict__ gxout)        // [T][B][256] permuted
{
    __shared__ float Wt[KPH][GG];                 // 32KB, [k][slot]
    __shared__ __align__(16) float xs[GXR][36];   // padded rows (bank spread)
    __shared__ float bs[GG];

    const int tid = threadIdx.x;
    const size_t base = (size_t)blockIdx.x * GXR;
    const int gc = tid & 63;          // gate group: slots 4gc..4gc+3
    const int rq = tid >> 6;          // row group: rows 8rq..8rq+7
    const int s  = tid;               // slot this thread loads W for
    const int wr = (s & 3) * 64 + (s >> 2);   // torch row of slot s

    bs[s] = bih[wr] + bhh[wr];

    unsigned long long acc[8][2];
#pragma unroll
    for (int r = 0; r < 8; r++) { acc[r][0] = 0ull; acc[r][1] = 0ull; }

#pragma unroll 1
    for (int ph = 0; ph < 2; ph++) {
        const int k0 = ph * KPH;
        if (ph) __syncthreads();      // all reads of previous phase done
        // W phase load: Wih[wr][k0..k0+32] -> Wt[k][s]  (STS conflict-free)
        {
            const float4* wp = reinterpret_cast<const float4*>(
                Wih + (size_t)wr * HH + k0);
#pragma unroll
            for (int i = 0; i < KPH / 4; i++) {
                float4 v = wp[i];
                Wt[4 * i + 0][s] = v.x;
                Wt[4 * i + 1][s] = v.y;
                Wt[4 * i + 2][s] = v.z;
                Wt[4 * i + 3][s] = v.w;
            }
        }
        // x phase load: 32 rows x 32 k, one float4 per thread
        {
            const int row = tid >> 3, c4 = (tid & 7) * 4;
            const float4 v = *reinterpret_cast<const float4*>(
                xseq + (base + row) * HH + k0 + c4);
            *reinterpret_cast<float4*>(&xs[row][c4]) = v;
        }
        __syncthreads();

#pragma unroll
        for (int k4 = 0; k4 < KPH / 4; k4++) {
            float4 xv[8];
#pragma unroll
            for (int r = 0; r < 8; r++)
                xv[r] = *reinterpret_cast<const float4*>(&xs[rq * 8 + r][k4 * 4]);
#pragma unroll
            for (int kk = 0; kk < 4; kk++) {
                const float4 wv = *reinterpret_cast<const float4*>(
                    &Wt[k4 * 4 + kk][4 * gc]);
                const unsigned long long w01 = pack2(wv.x, wv.y);
                const unsigned long long w23 = pack2(wv.z, wv.w);
#pragma unroll
                for (int r = 0; r < 8; r++) {
                    const float xr = (&xv[r].x)[kk];
                    const unsigned long long xx = pack2(xr, xr);
                    acc[r][0] = ffma2(w01, xx, acc[r][0]);
                    acc[r][1] = ffma2(w23, xx, acc[r][1]);
                }
            }
        }
    }

    const float4 bv = *reinterpret_cast<const float4*>(&bs[4 * gc]);
#pragma unroll
    for (int r = 0; r < 8; r++) {
        float2 a = unpack2(acc[r][0]);
        float2 b = unpack2(acc[r][1]);
        float4 o = make_float4(bv.x + a.x, bv.y + a.y, bv.z + b.x, bv.w + b.y);
        *reinterpret_cast<float4*>(
            &gxout[(base + rq * 8 + r) * GG + 4 * gc]) = o;
    }
}

// ---------------------------------------------------------------------------
// Recurrence: 256 threads, 2 rows x 4 warps/row; each thread owns TWO
// adjacent gate slots (2l, 2l+1) of hidden j -> every broadcast h load
// feeds 4 FFMA2 (halves the smem crossbar traffic, the measured R9
// bottleneck). Even lane = (i,f), odd lane = (g~,o) of the same j; one
// xor-1 shuffle pair exchanges them. float2 gx prefetch ring (MLP=8).
// grid = 128, block = 256.
// ---------------------------------------------------------------------------
__global__ __launch_bounds__(256, 1) void lstm_rec_kernel(
    const float* __restrict__ gx,     // [T][B][256] permuted
    const float* __restrict__ Whh,    // [256][64]
    float* __restrict__ hout)         // [T][B][64]
{
    __shared__ __align__(16) float h_s[2][RROWS * HH];
    const int tid = threadIdx.x;
    const int lane = tid & 31;
    const int r  = tid >> 7;          // batch row within CTA (0/1)
    const int qd = (tid >> 5) & 3;    // slot-quarter within row
    const int s0 = qd * 64 + 2 * lane;        // first slot
    const int j  = s0 >> 2;                    // hidden index
    const int par = lane & 1;         // 0: gates (i,f); 1: gates (g~,o)
    const int row0 = blockIdx.x * RROWS;
    const int wr0 = (s0 & 3) * 64 + (s0 >> 2);        // torch row, slot s0
    const int wr1 = ((s0 + 1) & 3) * 64 + ((s0 + 1) >> 2); // torch row, s0+1
    const int barid = 1 + r;

    // W_hh rows for both slots, k-packed f32x2
    unsigned long long wA[32], wB[32];
    {
        const double2* wp0 = reinterpret_cast<const double2*>(Whh + wr0 * HH);
        const double2* wp1 = reinterpret_cast<const double2*>(Whh + wr1 * HH);
#pragma unroll
        for (int i = 0; i < 16; i++) {
            double2 d0 = wp0[i];
            wA[2 * i]     = __double_as_longlong(d0.x);
            wA[2 * i + 1] = __double_as_longlong(d0.y);
            double2 d1 = wp1[i];
            wB[2 * i]     = __double_as_longlong(d1.x);
            wB[2 * i + 1] = __double_as_longlong(d1.y);
        }
    }

    const float2* gxp = reinterpret_cast<const float2*>(
        gx + (size_t)(row0 + r) * GG + s0);     // + t*BB*GG/2 per step (f2)

    float c = 0.0f;
    if (tid < RROWS * HH) h_s[0][tid] = 0.0f;
    __syncthreads();

    // prefetch ring: slot i holds gx pair for step (t : t % PF == i)
    float2 gring[PF];
#pragma unroll
    for (int i = 0; i < PF; i++)
        gring[i] = __ldg(gxp + (size_t)i * (BB * GG / 2));

    // activation constants: slot A is tanh only on odd lanes (gate g~)
    const float scA = par ? 1.0f : 0.5f;
    const float AmA = par ? 1.0f : 0.5f;
    const float BcA = par ? 0.0f : 0.5f;
    // slot B (gates f or o) is always sigmoid: 0.5*tanh(0.5v)+0.5

#pragma unroll 8
    for (int t = 0; t < TT; t++) {
        const int p = t & 1;
        const int slot = t & (PF - 1);
        const float2 gxv = gring[slot];
        if (t + PF < TT)
            gring[slot] = __ldg(gxp + (size_t)(t + PF) * (BB * GG / 2));

        // packed dots for both slots; each h load feeds 4 ffma2
        unsigned long long aA = 0ull, bA = 0ull, aB = 0ull, bB = 0ull;
        const double2* hp = reinterpret_cast<const double2*>(h_s[p] + r * HH);
#pragma unroll
        for (int i = 0; i < 16; i++) {
            double2 hv = hp[i];
            const unsigned long long hx = __double_as_longlong(hv.x);
            const unsigned long long hy = __double_as_longlong(hv.y);
            aA = ffma2(wA[2 * i],     hx, aA);
            bA = ffma2(wA[2 * i + 1], hy, bA);
            aB = ffma2(wB[2 * i],     hx, aB);
            bB = ffma2(wB[2 * i + 1], hy, bB);
        }
        float2 sA = unpack2(fadd2(aA, bA));
        float2 sB = unpack2(fadd2(aB, bB));
        const float vA = gxv.x + sA.x + sA.y;
        const float vB = gxv.y + sB.x + sB.y;

        const float actA = fmaf(tanh_approx(vA * scA), AmA, BcA);
        const float actB = fmaf(tanh_approx(vB * 0.5f), 0.5f, 0.5f);

        // xor-1 exchange: partner lane holds the other two gates of j
        const unsigned m = 0xffffffffu;
        const float oA = __shfl_xor_sync(m, actA, 1, 32);
        const float oB = __shfl_xor_sync(m, actB, 1, 32);

        const float ig = par ? oA   : actA;
        const float fg = par ? oB   : actB;
        const float Gg = par ? actA : oA;
        const float og = par ? actB : oB;

        c = fmaf(fg, c, ig * Gg);
        const float hv = og * tanh_approx(c);

        if (!par) {
            h_s[p ^ 1][r * HH + j] = hv;
            hout[((size_t)t * BB + row0 + r) * HH + j] = hv;
        }
        // per-row named barrier: this row's 4 warps (128 threads)
        asm volatile("bar.sync %0, %1;" :: "r"(barid), "r"(128) : "memory");
    }
}

// ---------------------------------------------------------------------------
// Final linear head. grid = T, block = 256.
// ---------------------------------------------------------------------------
__global__ __launch_bounds__(256) void lstm_lin_kernel(
    const float* __restrict__ hseq,   // [T][B][64]
    const float* __restrict__ Wl,     // [64]
    const float* __restrict__ bl,     // [1]
    float* __restrict__ out)          // [B][T]
{
    __shared__ float4 wl4[16];
    const int t = blockIdx.x;
    const int b = threadIdx.x;
    if (threadIdx.x < 16)
        wl4[threadIdx.x] = reinterpret_cast<const float4*>(Wl)[threadIdx.x];
    __syncthreads();

    const float4* hp = reinterpret_cast<const float4*>(hseq + ((size_t)t * BB + b) * HH);
    float acc = bl[0];
#pragma unroll
    for (int k4 = 0; k4 < 16; k4++) {
        const float4 h = hp[k4];
        const float4 w = wl4[k4];
        acc = fmaf(h.x, w.x, acc);
        acc = fmaf(h.y, w.y, acc);
        acc = fmaf(h.z, w.z, acc);
        acc = fmaf(h.w, w.w, acc);
    }
    out[(size_t)b * TT + t] = acc;
}

// ---------------------------------------------------------------------------
extern "C" void kernel_launch(void* const* d_in, const int* in_sizes, int n_in,
                              void* d_out, int out_size)
{
    (void)in_sizes; (void)n_in; (void)out_size;

    const float* x = (const float*)d_in[0];
    const float* Wih[5]; const float* Whh[5]; const float* bih[5]; const float* bhh[5];
    for (int l = 0; l < 5; l++) {
        Wih[l] = (const float*)d_in[1 + 4 * l];
        Whh[l] = (const float*)d_in[2 + 4 * l];
        bih[l] = (const float*)d_in[3 + 4 * l];
        bhh[l] = (const float*)d_in[4 + 4 * l];
    }
    const float* Wl = (const float*)d_in[21];
    const float* bl = (const float*)d_in[22];
    float* out = (float*)d_out;

    float *gx, *hA, *hB;
    cudaGetSymbolAddress((void**)&gx, g_gx);
    cudaGetSymbolAddress((void**)&hA, g_hA);
    cudaGetSymbolAddress((void**)&hB, g_hB);
    float* bufs[2] = { hA, hB };

    // layer 0
    lstm_gx0_kernel<<<TT, 256>>>(x, Wih[0], bih[0], bhh[0], gx);
    lstm_rec_kernel<<<BB / RROWS, 256>>>(gx, Whh[0], bufs[0]);

    // layers 1..4
    for (int l = 1; l < 5; l++) {
        const float* hin = bufs[(l - 1) & 1];
        float* ho = bufs[l & 1];
        lstm_gx_kernel<<<(TT * BB) / GXR, 256>>>(hin, Wih[l], bih[l], bhh[l], gx);
        lstm_rec_kernel<<<BB / RROWS, 256>>>(gx, Whh[l], ho);
    }

    // linear head (layer 4 wrote bufs[0])
    lstm_lin_kernel<<<TT, 256>>>(bufs[0], Wl, bl, out);
}

// round 11
// speedup vs baseline: 1.5313x; 1.0000x over previous
#include <cuda_runtime.h>
#include <cstdint>

#define TT 512
#define BB 256
#define HH 64
#define GG 256     // 4*H
#define RROWS 2    // batch rows per recurrence CTA -> 128 CTAs
#define PF 8       // gx prefetch depth (steps ahead); keep unroll pragma in sync
#define GXR 32     // batch-time rows per gx CTA
#define KPH 32     // K per smem phase in gx
static_assert(PF == 8, "update '#pragma unroll 8' in lstm_rec_kernel if PF changes");

// Scratch (device globals; no allocation in kernel_launch)
__device__ float g_gx[(size_t)TT * BB * GG];   // [T][B][4H] permuted col order
__device__ float g_hA[(size_t)TT * BB * HH];   // [T][B][H]
__device__ float g_hB[(size_t)TT * BB * HH];

// ---- packed fp32x2 helpers (Blackwell FFMA2 via PTX) ----------------------
__device__ __forceinline__ unsigned long long ffma2(unsigned long long a,
                                                    unsigned long long b,
                                                    unsigned long long c) {
    unsigned long long d;
    asm("fma.rn.f32x2 %0, %1, %2, %3;" : "=l"(d) : "l"(a), "l"(b), "l"(c));
    return d;
}
__device__ __forceinline__ unsigned long long fadd2(unsigned long long a,
                                                    unsigned long long b) {
    unsigned long long d;
    asm("add.rn.f32x2 %0, %1, %2;" : "=l"(d) : "l"(a), "l"(b));
    return d;
}
__device__ __forceinline__ float2 unpack2(unsigned long long v) {
    float2 r;
    asm("mov.b64 {%0, %1}, %2;" : "=f"(r.x), "=f"(r.y) : "l"(v));
    return r;
}
__device__ __forceinline__ unsigned long long pack2(float lo, float hi) {
    unsigned long long d;
    asm("mov.b64 %0, {%1, %2};" : "=l"(d) : "f"(lo), "f"(hi));
    return d;
}
// single-MUFU tanh (sm_75+)
__device__ __forceinline__ float tanh_approx(float x) {
    float y;
    asm("tanh.approx.f32 %0, %1;" : "=f"(y) : "f"(x));
    return y;
}

// gate index permutation: slot q <-> (j = q>>2, g = q&3), torch row = g*64+j
__device__ __forceinline__ int perm_row(int q) { return (q & 3) * 64 + (q >> 2); }

// ---------------------------------------------------------------------------
// Layer 0 input projection (d_in = 2), writes permuted gx layout.
// grid = T, block = 256
// ---------------------------------------------------------------------------
__global__ __launch_bounds__(256) void lstm_gx0_kernel(
    const float* __restrict__ x,      // [B][T][2]
    const float* __restrict__ Wih,    // [256][2]
    const float* __restrict__ bih,
    const float* __restrict__ bhh,
    float* __restrict__ gxout)        // [T][B][256] permuted
{
    __shared__ float xs[2 * BB];
    const int t = blockIdx.x;
    const int tid = threadIdx.x;
    const int wr = perm_row(tid);

    xs[2 * tid]     = x[((size_t)tid * TT + t) * 2 + 0];
    xs[2 * tid + 1] = x[((size_t)tid * TT + t) * 2 + 1];
    const float w0   = Wih[wr * 2];
    const float w1   = Wih[wr * 2 + 1];
    const float bias = bih[wr] + bhh[wr];
    __syncthreads();

    float* op = gxout + (size_t)t * BB * GG + tid;
#pragma unroll 4
    for (int r = 0; r < BB; r++) {
        op[r * GG] = fmaf(xs[2 * r], w0, fmaf(xs[2 * r + 1], w1, bias));
    }
}

// ---------------------------------------------------------------------------
// Layers 1..4 input projection v3: [T*B,64] x [64,256] + bias.
// k-major x in smem as row-pair float2 (packed operand straight from LDS,
// no per-element MOV splats); W k-major, splat 4 MOVs per k amortized over
// 16 FFMA2. Thread tile: 8 rows x 4 gates (acc[gate][rowpair]).
// grid = T*B/32, block = 256.
// ---------------------------------------------------------------------------
__global__ __launch_bounds__(256, 2) void lstm_gx_kernel(
    const float* __restrict__ xseq,   // [T][B][64]
    const float* __restrict__ Wih,    // [256][64]
    const float* __restrict__ bih,
    const float* __restrict__ bhh,
    float* __restrict__ gxout)        // [T][B][256] permuted
{
    __shared__ float Wt[KPH][GG];                       // 32KB [k][slot]
    __shared__ __align__(16) float2 xsT[KPH][18];       // [k][rowpair], padded
    __shared__ float bs[GG];

    const int tid = threadIdx.x;
    const size_t base = (size_t)blockIdx.x * GXR;
    const int gc = tid & 63;          // gate group: slots 4gc..4gc+3
    const int rq = tid >> 6;          // row group: rows 8rq..8rq+7
    const int wr = (tid & 3) * 64 + (tid >> 2);   // torch row of slot tid

    bs[tid] = bih[wr] + bhh[wr];

    unsigned long long acc[4][4];     // [gate][rowpair]
#pragma unroll
    for (int g = 0; g < 4; g++)
#pragma unroll
        for (int rp = 0; rp < 4; rp++) acc[g][rp] = 0ull;

#pragma unroll 1
    for (int ph = 0; ph < 2; ph++) {
        const int k0 = ph * KPH;
        if (ph) __syncthreads();      // all reads of previous phase done
        // W phase load: Wih[wr][k0..k0+31] -> Wt[k][tid]
        {
            const float4* wp = reinterpret_cast<const float4*>(
                Wih + (size_t)wr * HH + k0);
#pragma unroll
            for (int i = 0; i < KPH / 4; i++) {
                float4 v = wp[i];
                Wt[4 * i + 0][tid] = v.x;
                Wt[4 * i + 1][tid] = v.y;
                Wt[4 * i + 2][tid] = v.z;
                Wt[4 * i + 3][tid] = v.w;
            }
        }
        // x transposed phase load: row = tid>>3 (0..31), cols c4=(tid&7)*4
        {
            const int row = tid >> 3, c4 = (tid & 7) * 4;
            const float4 v = *reinterpret_cast<const float4*>(
                xseq + (base + row) * HH + k0 + c4);
            const int rp = row >> 1, comp = row & 1;
            reinterpret_cast<float*>(&xsT[c4 + 0][rp])[comp] = v.x;
            reinterpret_cast<float*>(&xsT[c4 + 1][rp])[comp] = v.y;
            reinterpret_cast<float*>(&xsT[c4 + 2][rp])[comp] = v.z;
            reinterpret_cast<float*>(&xsT[c4 + 3][rp])[comp] = v.w;
        }
        __syncthreads();

#pragma unroll 2
        for (int k = 0; k < KPH; k++) {
            const float4 wq = *reinterpret_cast<const float4*>(&Wt[k][4 * gc]);
            const ulonglong2 xv0 =
                *reinterpret_cast<const ulonglong2*>(&xsT[k][4 * rq]);
            const ulonglong2 xv1 =
                *reinterpret_cast<const ulonglong2*>(&xsT[k][4 * rq + 2]);
            const unsigned long long ws[4] = {
                pack2(wq.x, wq.x), pack2(wq.y, wq.y),
                pack2(wq.z, wq.z), pack2(wq.w, wq.w) };
#pragma unroll
            for (int g = 0; g < 4; g++) {
                acc[g][0] = ffma2(ws[g], xv0.x, acc[g][0]);
                acc[g][1] = ffma2(ws[g], xv0.y, acc[g][1]);
                acc[g][2] = ffma2(ws[g], xv1.x, acc[g][2]);
                acc[g][3] = ffma2(ws[g], xv1.y, acc[g][3]);
            }
        }
    }

    // epilogue: per rowpair, transpose to row-major and STG.128 with bias
    const float4 bv = *reinterpret_cast<const float4*>(&bs[4 * gc]);
#pragma unroll
    for (int rp = 0; rp < 4; rp++) {
        float2 g0 = unpack2(acc[0][rp]);
        float2 g1 = unpack2(acc[1][rp]);
        float2 g2 = unpack2(acc[2][rp]);
        float2 g3 = unpack2(acc[3][rp]);
        float4 lo = make_float4(bv.x + g0.x, bv.y + g1.x, bv.z + g2.x, bv.w + g3.x);
        float4 hi = make_float4(bv.x + g0.y, bv.y + g1.y, bv.z + g2.y, bv.w + g3.y);
        *reinterpret_cast<float4*>(
            &gxout[(base + rq * 8 + 2 * rp + 0) * GG + 4 * gc]) = lo;
        *reinterpret_cast<float4*>(
            &gxout[(base + rq * 8 + 2 * rp + 1) * GG + 4 * gc]) = hi;
    }
}

// ---------------------------------------------------------------------------
// Recurrence: 256 threads, 2 rows x 4 warps/row; 2 adjacent slots/thread.
// Row 1 is phase-offset by a ~190-cycle dummy FMA chain at start so the two
// warps sharing each SMSP (one per row) stop stalling in lockstep and
// interleave their serial chains. grid = 128, block = 256.
// ---------------------------------------------------------------------------
__global__ __launch_bounds__(256, 1) void lstm_rec_kernel(
    const float* __restrict__ gx,     // [T][B][256] permuted
    const float* __restrict__ Whh,    // [256][64]
    float* __restrict__ hout)         // [T][B][64]
{
    __shared__ __align__(16) float h_s[2][RROWS * HH];
    const int tid = threadIdx.x;
    const int lane = tid & 31;
    const int r  = tid >> 7;          // batch row within CTA (0/1)
    const int qd = (tid >> 5) & 3;    // slot-quarter within row
    const int s0 = qd * 64 + 2 * lane;        // first slot
    const int j  = s0 >> 2;                    // hidden index
    const int par = lane & 1;         // 0: gates (i,f); 1: gates (g~,o)
    const int row0 = blockIdx.x * RROWS;
    const int wr0 = (s0 & 3) * 64 + (s0 >> 2);        // torch row, slot s0
    const int wr1 = ((s0 + 1) & 3) * 64 + ((s0 + 1) >> 2); // torch row, s0+1
    const int barid = 1 + r;

    // W_hh rows for both slots, k-packed f32x2
    unsigned long long wA[32], wB[32];
    {
        const double2* wp0 = reinterpret_cast<const double2*>(Whh + wr0 * HH);
        const double2* wp1 = reinterpret_cast<const double2*>(Whh + wr1 * HH);
#pragma unroll
        for (int i = 0; i < 16; i++) {
            double2 d0 = wp0[i];
            wA[2 * i]     = __double_as_longlong(d0.x);
            wA[2 * i + 1] = __double_as_longlong(d0.y);
            double2 d1 = wp1[i];
            wB[2 * i]     = __double_as_longlong(d1.x);
            wB[2 * i + 1] = __double_as_longlong(d1.y);
        }
    }

    const float2* gxp = reinterpret_cast<const float2*>(
        gx + (size_t)(row0 + r) * GG + s0);     // + t*BB*GG/2 per step (f2)

    float c = 0.0f;
    if (tid < RROWS * HH) h_s[0][tid] = 0.0f;
    __syncthreads();

    // prefetch ring: slot i holds gx pair for step (t : t % PF == i)
    float2 gring[PF];
#pragma unroll
    for (int i = 0; i < PF; i++)
        gring[i] = __ldg(gxp + (size_t)i * (BB * GG / 2));

    // one-time desync: delay row 1 ~190 cycles so SMSP-sharing warps of the
    // two rows stop phase-locking on identical stall points
    if (r == 1) {
        float dly = (float)(lane + 7);
#pragma unroll
        for (int i = 0; i < 48; i++)
            dly = fmaf(dly, 0.99999988f, 1.0e-7f);
        if (dly == -1.0f) h_s[0][0] = 0.0f;    // unreachable; keeps the chain
    }

    // activation constants: slot A is tanh only on odd lanes (gate g~)
    const float scA = par ? 1.0f : 0.5f;
    const float AmA = par ? 1.0f : 0.5f;
    const float BcA = par ? 0.0f : 0.5f;
    // slot B (gates f or o) is always sigmoid: 0.5*tanh(0.5v)+0.5

#pragma unroll 8
    for (int t = 0; t < TT; t++) {
        const int p = t & 1;
        const int slot = t & (PF - 1);
        const float2 gxv = gring[slot];
        if (t + PF < TT)
            gring[slot] = __ldg(gxp + (size_t)(t + PF) * (BB * GG / 2));

        // packed dots for both slots; each h load feeds 4 ffma2
        unsigned long long aA = 0ull, bA = 0ull, aB = 0ull, bB = 0ull;
        const double2* hp = reinterpret_cast<const double2*>(h_s[p] + r * HH);
#pragma unroll
        for (int i = 0; i < 16; i++) {
            double2 hv = hp[i];
            const unsigned long long hx = __double_as_longlong(hv.x);
            const unsigned long long hy = __double_as_longlong(hv.y);
            aA = ffma2(wA[2 * i],     hx, aA);
            bA = ffma2(wA[2 * i + 1], hy, bA);
            aB = ffma2(wB[2 * i],     hx, aB);
            bB = ffma2(wB[2 * i + 1], hy, bB);
        }
        float2 sA = unpack2(fadd2(aA, bA));
        float2 sB = unpack2(fadd2(aB, bB));
        const float vA = gxv.x + sA.x + sA.y;
        const float vB = gxv.y + sB.x + sB.y;

        const float actA = fmaf(tanh_approx(vA * scA), AmA, BcA);
        const float actB = fmaf(tanh_approx(vB * 0.5f), 0.5f, 0.5f);

        // xor-1 exchange: partner lane holds the other two gates of j
        const unsigned m = 0xffffffffu;
        const float oA = __shfl_xor_sync(m, actA, 1, 32);
        const float oB = __shfl_xor_sync(m, actB, 1, 32);

        const float ig = par ? oA   : actA;
        const float fg = par ? oB   : actB;
        const float Gg = par ? actA : oA;
        const float og = par ? actB : oB;

        c = fmaf(fg, c, ig * Gg);
        const float hv = og * tanh_approx(c);

        if (!par) {
            h_s[p ^ 1][r * HH + j] = hv;
            hout[((size_t)t * BB + row0 + r) * HH + j] = hv;
        }
        // per-row named barrier: this row's 4 warps (128 threads)
        asm volatile("bar.sync %0, %1;" :: "r"(barid), "r"(128) : "memory");
    }
}

// ---------------------------------------------------------------------------
// Final linear head. grid = T, block = 256.
// ---------------------------------------------------------------------------
__global__ __launch_bounds__(256) void lstm_lin_kernel(
    const float* __restrict__ hseq,   // [T][B][64]
    const float* __restrict__ Wl,     // [64]
    const float* __restrict__ bl,     // [1]
    float* __restrict__ out)          // [B][T]
{
    __shared__ float4 wl4[16];
    const int t = blockIdx.x;
    const int b = threadIdx.x;
    if (threadIdx.x < 16)
        wl4[threadIdx.x] = reinterpret_cast<const float4*>(Wl)[threadIdx.x];
    __syncthreads();

    const float4* hp = reinterpret_cast<const float4*>(hseq + ((size_t)t * BB + b) * HH);
    float acc = bl[0];
#pragma unroll
    for (int k4 = 0; k4 < 16; k4++) {
        const float4 h = hp[k4];
        const float4 w = wl4[k4];
        acc = fmaf(h.x, w.x, acc);
        acc = fmaf(h.y, w.y, acc);
        acc = fmaf(h.z, w.z, acc);
        acc = fmaf(h.w, w.w, acc);
    }
    out[(size_t)b * TT + t] = acc;
}

// ---------------------------------------------------------------------------
extern "C" void kernel_launch(void* const* d_in, const int* in_sizes, int n_in,
                              void* d_out, int out_size)
{
    (void)in_sizes; (void)n_in; (void)out_size;

    const float* x = (const float*)d_in[0];
    const float* Wih[5]; const float* Whh[5]; const float* bih[5]; const float* bhh[5];
    for (int l = 0; l < 5; l++) {
        Wih[l] = (const float*)d_in[1 + 4 * l];
        Whh[l] = (const float*)d_in[2 + 4 * l];
        bih[l] = (const float*)d_in[3 + 4 * l];
        bhh[l] = (const float*)d_in[4 + 4 * l];
    }
    const float* Wl = (const float*)d_in[21];
    const float* bl = (const float*)d_in[22];
    float* out = (float*)d_out;

    float *gx, *hA, *hB;
    cudaGetSymbolAddress((void**)&gx, g_gx);
    cudaGetSymbolAddress((void**)&hA, g_hA);
    cudaGetSymbolAddress((void**)&hB, g_hB);
    float* bufs[2] = { hA, hB };

    // layer 0
    lstm_gx0_kernel<<<TT, 256>>>(x, Wih[0], bih[0], bhh[0], gx);
    lstm_rec_kernel<<<BB / RROWS, 256>>>(gx, Whh[0], bufs[0]);

    // layers 1..4
    for (int l = 1; l < 5; l++) {
        const float* hin = bufs[(l - 1) & 1];
        float* ho = bufs[l & 1];
        lstm_gx_kernel<<<(TT * BB) / GXR, 256>>>(hin, Wih[l], bih[l], bhh[l], gx);
        lstm_rec_kernel<<<BB / RROWS, 256>>>(gx, Whh[l], ho);
    }

    // linear head (layer 4 wrote bufs[0])
    lstm_lin_kernel<<<TT, 256>>>(bufs[0], Wl, bl, out);
}